// round 1
// baseline (speedup 1.0000x reference)
#include <cuda_runtime.h>
#include <math.h>
#include <stdint.h>

#define BB 32
#define AA 9
#define HH 128
#define WW 128
#define NN (AA*HH*WW)      /* 147456 */
#define PRE 6000
#define POST 300
#define CAP 8192
#define NMS_T 0.7f

// ---------------- device scratch (static: no allocation allowed) ----------------
__device__ float              g_base[AA*4];
__device__ int                g_cnt[BB];
__device__ unsigned           g_thresh[BB];
__device__ float              g_scores[BB*NN];          // ~18.9 MB
__device__ unsigned long long g_items[BB*CAP];          // 2 MB
__device__ float4             g_cand[BB*PRE];
__device__ unsigned           g_candKey[BB*PRE];

__device__ __forceinline__ unsigned keyOf(float f){
    unsigned u = __float_as_uint(f);
    return (u & 0x80000000u) ? ~u : (u | 0x80000000u);
}

// decode + clip, identical math for filter pass and candidate pass
__device__ __forceinline__ void decode_box(const float* __restrict__ pred,
                                           int b, int a, int y, int x,
                                           float imh, float imw,
                                           float& x1, float& y1, float& x2, float& y2,
                                           float& ws, float& hs){
    float sx = (float)(x*16), sy = (float)(y*16);
    float a0 = g_base[a*4+0]+sx, a1 = g_base[a*4+1]+sy;
    float a2 = g_base[a*4+2]+sx, a3 = g_base[a*4+3]+sy;
    float aw = a2-a0+1.0f, ah = a3-a1+1.0f;
    float cx = a0+0.5f*aw,  cy = a1+0.5f*ah;
    int base = ((b*4*AA + 4*a)*HH + y)*WW + x;
    float dx = pred[base];
    float dy = pred[base +   HH*WW];
    float dw = pred[base + 2*HH*WW];
    float dh = pred[base + 3*HH*WW];
    float pcx = dx*aw+cx, pcy = dy*ah+cy;
    float pw = expf(dw)*aw, ph = expf(dh)*ah;
    x1 = pcx-0.5f*pw; y1 = pcy-0.5f*ph; x2 = pcx+0.5f*pw; y2 = pcy+0.5f*ph;
    x1 = fminf(fmaxf(x1,0.0f), imw-1.0f);
    y1 = fminf(fmaxf(y1,0.0f), imh-1.0f);
    x2 = fminf(fmaxf(x2,0.0f), imw-1.0f);
    y2 = fminf(fmaxf(y2,0.0f), imh-1.0f);
    ws = x2-x1+1.0f; hs = y2-y1+1.0f;
}

// ---------------- K0: anchors (fp64, banker's rounding = np.round) + zero counters
__global__ void k_init(){
    int tid = threadIdx.x;
    if (tid < BB) g_cnt[tid] = 0;
    if (tid == 0){
        const double ratios[3] = {0.5, 1.0, 2.0};
        const double scales[3] = {8.0, 16.0, 32.0};
        double bx1=0.0, by1=0.0, bx2=15.0, by2=15.0;
        double w = bx2-bx1+1.0, h = by2-by1+1.0;
        double xc = bx1+0.5*(w-1.0), yc = by1+0.5*(h-1.0);
        double size = w*h;
        for (int r=0;r<3;r++){
            double ws = rint(sqrt(size/ratios[r]));
            double hs = rint(ws*ratios[r]);
            double rx1 = xc-0.5*(ws-1.0), ry1 = yc-0.5*(hs-1.0);
            double rx2 = xc+0.5*(ws-1.0), ry2 = yc+0.5*(hs-1.0);
            double w2 = rx2-rx1+1.0, h2 = ry2-ry1+1.0;
            double xc2 = rx1+0.5*(w2-1.0), yc2 = ry1+0.5*(h2-1.0);
            for (int s=0;s<3;s++){
                double ws2 = w2*scales[s], hs2 = h2*scales[s];
                int a = r*3+s;
                g_base[a*4+0] = (float)(xc2-0.5*(ws2-1.0));
                g_base[a*4+1] = (float)(yc2-0.5*(hs2-1.0));
                g_base[a*4+2] = (float)(xc2+0.5*(ws2-1.0));
                g_base[a*4+3] = (float)(yc2+0.5*(hs2-1.0));
            }
        }
    }
}

// ---------------- K1: score + min-size filter ----------------
__global__ void k_score(const float* __restrict__ cls, const float* __restrict__ pred,
                        const float* __restrict__ info){
    int idx = blockIdx.x*blockDim.x + threadIdx.x;
    if (idx >= BB*NN) return;
    int x = idx & (WW-1);
    int y = (idx >> 7) & (HH-1);
    int t = idx >> 14;            // b*AA + a  (layout [b][a][y][x])
    int a = t % AA, b = t / AA;
    float imh = __ldg(&info[b*3+0]);
    float imw = __ldg(&info[b*3+1]);
    float sc  = __ldg(&info[b*3+2]);
    float x1,y1,x2,y2,ws,hs;
    decode_box(pred,b,a,y,x,imh,imw,x1,y1,x2,y2,ws,hs);
    float minsz = 16.0f*sc;
    float s = cls[((b*2*AA + AA + a)*HH + y)*WW + x];
    if (!(ws >= minsz && hs >= minsz)) s = -1e30f;
    g_scores[idx] = s;
}

// ---------------- fill item buffer with zeros (sort padding) ----------------
__global__ void k_fill(){
    int i = blockIdx.x*blockDim.x + threadIdx.x;
    if (i < BB*CAP) g_items[i] = 0ull;
}

// ---------------- K2: exact radix-select of 6000th-largest key per image --------
__global__ void k_select(){
    int b = blockIdx.x;
    const float* sc = g_scores + b*NN;
    __shared__ unsigned h0[2048], h1[2048];
    __shared__ unsigned s_prefix, s_krem, s_found, s_next;
    int tid = threadIdx.x;
    int lane = tid & 31;
    if (tid==0){ s_krem = PRE; s_prefix = 0; }
    for (int lvl=0; lvl<3; lvl++){
        int bins  = (lvl==2)?1024:2048;
        int shift = (lvl==0)?21:((lvl==1)?10:0);
        __syncthreads();
        unsigned pref = s_prefix;
        unsigned krem = s_krem;
        for (int i=tid;i<bins;i+=1024) h0[i]=0;
        __syncthreads();
        // histogram with warp-aggregated shared atomics
        for (int p=tid;p<NN;p+=1024){
            unsigned key = keyOf(sc[p]);
            bool ok = (lvl==0) || (lvl==1 ? ((key>>21)==pref) : ((key>>10)==pref));
            unsigned bin = ok ? ((key>>shift)&(bins-1)) : 0xFFFFFFFFu;
            unsigned peers = __match_any_sync(0xFFFFFFFFu, bin);
            int leader = __ffs(peers)-1;
            if (ok && lane==leader) atomicAdd(&h0[bin], (unsigned)__popc(peers));
        }
        __syncthreads();
        // suffix sum (count of elements in bins >= i)
        unsigned* src = h0; unsigned* dst = h1;
        for (int off=1; off<bins; off<<=1){
            for (int i=tid;i<bins;i+=1024)
                dst[i] = src[i] + ((i+off<bins)? src[i+off] : 0u);
            __syncthreads();
            unsigned* tmp = src; src = dst; dst = tmp;
        }
        // find the unique bin with sfx[b] >= krem > sfx[b+1]
        for (int i=tid;i<bins;i+=1024){
            unsigned si = src[i];
            unsigned nx = (i+1<bins)? src[i+1] : 0u;
            if (si >= krem && nx < krem){ s_found = (unsigned)i; s_next = nx; }
        }
        __syncthreads();
        if (tid==0){
            s_krem = krem - s_next;
            if (lvl==0)      s_prefix = s_found;
            else if (lvl==1) s_prefix = (s_prefix<<11) | s_found;
            else             s_prefix = (s_prefix<<10) | s_found;
        }
    }
    __syncthreads();
    if (tid==0) g_thresh[b] = s_prefix;   // exact key of the 6000th-largest score
}

// ---------------- K3: compact key >= K items (warp-aggregated global atomics) ---
__global__ void k_compact(){
    int b = blockIdx.y;
    unsigned K = g_thresh[b];
    const float* sc = g_scores + b*NN;
    int tid = threadIdx.x;
    int lane = tid & 31;
    int start = blockIdx.x*blockDim.x + tid;
    int stride = gridDim.x*blockDim.x;     // divides NN exactly (8*1024 -> 18 iters)
    for (int p=start; p<NN; p+=stride){
        unsigned key = keyOf(sc[p]);
        bool ok = (key >= K);
        unsigned m = __ballot_sync(0xFFFFFFFFu, ok);
        if (m){
            int leader = __ffs(m)-1;
            int base = 0;
            if (lane==leader) base = atomicAdd(&g_cnt[b], __popc(m));
            base = __shfl_sync(0xFFFFFFFFu, base, leader);
            if (ok){
                int pos = base + __popc(m & ((1u<<lane)-1u));
                if (pos < CAP){
                    int a   = p >> 14;
                    int rem = p & 16383;
                    int y = rem >> 7, x = rem & 127;
                    unsigned refidx = (unsigned)((y*WW + x)*AA + a);
                    g_items[b*CAP + pos] =
                        ((unsigned long long)key << 32) | (unsigned)(~refidx);
                }
            }
        }
    }
}

// ---------------- K4: per-image bitonic sort (desc) + candidate decode ----------
__global__ void k_sort(const float* __restrict__ pred, const float* __restrict__ info){
    extern __shared__ unsigned long long sm[];
    int b = blockIdx.x, tid = threadIdx.x;
    for (int i=tid;i<CAP;i+=1024) sm[i] = g_items[b*CAP+i];
    __syncthreads();
    for (int k=2;k<=CAP;k<<=1){
        for (int j=k>>1;j>0;j>>=1){
            for (int t=tid;t<CAP;t+=1024){
                int ixj = t ^ j;
                if (ixj > t){
                    unsigned long long va = sm[t], vb = sm[ixj];
                    bool desc = ((t & k) == 0);
                    if ((va < vb) == desc){ sm[t]=vb; sm[ixj]=va; }
                }
            }
            __syncthreads();
        }
    }
    float imh = info[b*3+0], imw = info[b*3+1];
    unsigned negk = keyOf(-1e30f);
    for (int i=tid;i<PRE;i+=1024){
        unsigned long long item = sm[i];
        unsigned key = (unsigned)(item>>32);
        float4 box = make_float4(0.f,0.f,0.f,0.f);
        if (key > negk){
            unsigned refidx = ~((unsigned)item);
            int a = (int)(refidx % AA);
            int cell = (int)(refidx / AA);
            int x = cell & 127, y = cell >> 7;
            float x1,y1,x2,y2,ws,hs;
            decode_box(pred,b,a,y,x,imh,imw,x1,y1,x2,y2,ws,hs);
            box = make_float4(x1,y1,x2,y2);
        }
        g_cand[b*PRE+i]    = box;
        g_candKey[b*PRE+i] = key;
    }
}

// ---------------- K5: greedy sorted NMS + output ----------------
__global__ void k_nms(float* __restrict__ out){
    extern __shared__ char smem[];
    float* sx1 = (float*)smem;
    float* sy1 = sx1 + PRE;
    float* sx2 = sy1 + PRE;
    float* sy2 = sx2 + PRE;
    unsigned char* ssup = (unsigned char*)(sy2 + PRE);
    __shared__ int s_keep[POST];
    __shared__ int s_cur, s_nk, s_head;
    int b = blockIdx.x, tid = threadIdx.x;
    unsigned negk = keyOf(-1e30f);

    float cx1[6],cy1[6],cx2[6],cy2[6],car[6];
    #pragma unroll
    for (int c=0;c<6;c++){
        int i = tid + c*1024;
        if (i < PRE){
            float4 bx = g_cand[b*PRE+i];
            sx1[i]=bx.x; sy1[i]=bx.y; sx2[i]=bx.z; sy2[i]=bx.w;
            cx1[c]=bx.x; cy1[c]=bx.y; cx2[c]=bx.z; cy2[c]=bx.w;
            car[c]=(bx.z-bx.x+1.0f)*(bx.w-bx.y+1.0f);
            ssup[i] = (g_candKey[b*PRE+i] <= negk) ? (unsigned char)1 : (unsigned char)0;
        }
    }
    if (tid==0){ s_nk=0; s_head=0; }
    __syncthreads();

    while (true){
        if (tid < 32){
            int found = -1;
            if (s_nk < POST){
                for (int i0=s_head; i0<PRE; i0+=32){
                    int ii = i0 + tid;
                    bool ok = (ii<PRE) && (ssup[ii]==0);
                    unsigned m = __ballot_sync(0xFFFFFFFFu, ok);
                    if (m){ found = i0 + __ffs(m) - 1; break; }
                }
            }
            if (tid==0){
                s_cur = found;
                if (found>=0){ s_keep[s_nk]=found; s_nk++; s_head = found+1; }
            }
        }
        __syncthreads();
        int cur = s_cur;
        if (cur < 0) break;
        float kx1=sx1[cur], ky1=sy1[cur], kx2=sx2[cur], ky2=sy2[cur];
        float kar = (kx2-kx1+1.0f)*(ky2-ky1+1.0f);
        #pragma unroll
        for (int c=0;c<6;c++){
            int i = tid + c*1024;
            if (i < PRE){
                float xx1=fmaxf(kx1,cx1[c]), yy1=fmaxf(ky1,cy1[c]);
                float xx2=fminf(kx2,cx2[c]), yy2=fminf(ky2,cy2[c]);
                float iw = fmaxf(xx2-xx1+1.0f,0.0f);
                float ih = fmaxf(yy2-yy1+1.0f,0.0f);
                float inter = iw*ih;
                float iou = inter / fmaxf(kar + car[c] - inter, 1e-6f);
                if (iou > NMS_T) ssup[i] = 1;
            }
        }
        __syncthreads();
    }

    if (tid < POST){
        int row = (b*POST + tid)*5;
        float v1=0.f,v2=0.f,v3=0.f,v4=0.f;
        if (tid < s_nk){
            int j = s_keep[tid];
            v1=sx1[j]; v2=sy1[j]; v3=sx2[j]; v4=sy2[j];
        }
        out[row+0]=(float)b; out[row+1]=v1; out[row+2]=v2; out[row+3]=v3; out[row+4]=v4;
    }
}

// ---------------- launcher ----------------
extern "C" void kernel_launch(void* const* d_in, const int* in_sizes, int n_in,
                              void* d_out, int out_size){
    const float* cls  = (const float*)d_in[0];
    const float* pred = (const float*)d_in[1];
    const float* info = (const float*)d_in[2];
    float* out = (float*)d_out;

    cudaFuncSetAttribute(k_sort, cudaFuncAttributeMaxDynamicSharedMemorySize, CAP*8);
    cudaFuncSetAttribute(k_nms,  cudaFuncAttributeMaxDynamicSharedMemorySize, PRE*4*4 + PRE + 64);

    k_init<<<1,32>>>();
    k_score<<<(BB*NN+255)/256,256>>>(cls,pred,info);
    k_fill<<<(BB*CAP+511)/512,512>>>();
    k_select<<<BB,1024>>>();
    k_compact<<<dim3(8,BB),1024>>>();
    k_sort<<<BB,1024, CAP*8>>>(pred,info);
    k_nms<<<BB,1024, PRE*4*4 + PRE + 64>>>(out);
}

// round 3
// speedup vs baseline: 1.1447x; 1.1447x over previous
#include <cuda_runtime.h>
#include <math.h>
#include <stdint.h>

#define BB 32
#define AA 9
#define HH 128
#define WW 128
#define NN (AA*HH*WW)      /* 147456 */
#define PRE 6000
#define POST 300
#define CAP 8192
#define NMS_T 0.7f
#define NBIN 2048

// Anchors: generate_anchors(16,[.5,1,2],[8,16,32]) — exact integers, verified vs numpy.
__constant__ float c_anch[AA*4] = {
   -84.f, -40.f,  99.f,  55.f,
  -176.f, -88.f, 191.f, 103.f,
  -360.f,-184.f, 375.f, 199.f,
   -56.f, -56.f,  71.f,  71.f,
  -120.f,-120.f, 135.f, 135.f,
  -248.f,-248.f, 263.f, 263.f,
   -36.f, -80.f,  51.f,  95.f,
   -80.f,-168.f,  95.f, 183.f,
  -168.f,-344.f, 183.f, 359.f
};

// ---------------- device scratch ----------------
__device__ int                g_cnt[BB];
__device__ unsigned           g_thresh[BB];
__device__ unsigned           g_hist[BB*NBIN];
__device__ unsigned           g_keys[BB*NN];            // order-preserving keys
__device__ unsigned long long g_items[BB*CAP];
__device__ float4             g_cand[BB*PRE];
__device__ unsigned           g_candKey[BB*PRE];

__device__ __forceinline__ unsigned keyOf(float f){
    unsigned u = __float_as_uint(f);
    return (u & 0x80000000u) ? ~u : (u | 0x80000000u);
}

__device__ __forceinline__ void decode_box(const float* __restrict__ pred,
                                           int b, int a, int y, int x,
                                           float imh, float imw,
                                           float& x1, float& y1, float& x2, float& y2,
                                           float& ws, float& hs){
    float sx = (float)(x*16), sy = (float)(y*16);
    float a0 = c_anch[a*4+0]+sx, a1 = c_anch[a*4+1]+sy;
    float a2 = c_anch[a*4+2]+sx, a3 = c_anch[a*4+3]+sy;
    float aw = a2-a0+1.0f, ah = a3-a1+1.0f;
    float cx = a0+0.5f*aw,  cy = a1+0.5f*ah;
    int base = ((b*4*AA + 4*a)*HH + y)*WW + x;
    float dx = pred[base];
    float dy = pred[base +   HH*WW];
    float dw = pred[base + 2*HH*WW];
    float dh = pred[base + 3*HH*WW];
    float pcx = dx*aw+cx, pcy = dy*ah+cy;
    float pw = expf(dw)*aw, ph = expf(dh)*ah;
    x1 = pcx-0.5f*pw; y1 = pcy-0.5f*ph; x2 = pcx+0.5f*pw; y2 = pcy+0.5f*ph;
    x1 = fminf(fmaxf(x1,0.0f), imw-1.0f);
    y1 = fminf(fmaxf(y1,0.0f), imh-1.0f);
    x2 = fminf(fmaxf(x2,0.0f), imw-1.0f);
    y2 = fminf(fmaxf(y2,0.0f), imh-1.0f);
    ws = x2-x1+1.0f; hs = y2-y1+1.0f;
}

// key -> histogram bin (monotone). Fine bins over key >= keyOf(0.5)=0xBF000000,
// (13-bit key granularity), coarse below.
__device__ __forceinline__ unsigned binOf(unsigned key){
    if (key >= 0xBF000000u){
        unsigned b = 1024u + ((key - 0xBF000000u) >> 13);
        return b > 2047u ? 2047u : b;
    }
    unsigned b = key >> 22;
    return b > 1023u ? 1023u : b;
}
__device__ __forceinline__ unsigned binStartKey(unsigned t){
    return (t >= 1024u) ? (0xBF000000u + ((t - 1024u) << 13)) : (t << 22);
}

// ---------------- K0: zero hist + counters ----------------
__global__ void k_init(){
    int i = blockIdx.x*blockDim.x + threadIdx.x;
    if (i < BB*NBIN) g_hist[i] = 0u;
    if (i < BB) g_cnt[i] = 0;
}

// ---------------- K1: score+filter -> keys, fused histogram ----------------
__global__ void k_score(const float* __restrict__ cls, const float* __restrict__ pred,
                        const float* __restrict__ info){
    __shared__ unsigned h[NBIN];
    int b = blockIdx.y;
    int tid = threadIdx.x, lane = tid & 31;
    float imh = __ldg(&info[b*3+0]);
    float imw = __ldg(&info[b*3+1]);
    float minsz = 16.0f*__ldg(&info[b*3+2]);
    for (int i=tid;i<NBIN;i+=1024) h[i]=0u;
    __syncthreads();
    #pragma unroll
    for (int it=0; it<8; it++){
        int e = blockIdx.x*8192 + it*1024 + tid;   // index within image
        int a = e >> 14;
        int y = (e >> 7) & 127;
        int x = e & 127;
        float x1,y1,x2,y2,ws,hs;
        decode_box(pred,b,a,y,x,imh,imw,x1,y1,x2,y2,ws,hs);
        float s = cls[((b*2*AA + AA + a)*HH + y)*WW + x];
        if (!(ws >= minsz && hs >= minsz)) s = -1e30f;
        unsigned key = keyOf(s);
        g_keys[b*NN + e] = key;
        unsigned bin = binOf(key);
        unsigned peers = __match_any_sync(0xFFFFFFFFu, bin);
        if (lane == __ffs(peers)-1) atomicAdd(&h[bin], (unsigned)__popc(peers));
    }
    __syncthreads();
    for (int i=tid;i<NBIN;i+=1024)
        if (h[i]) atomicAdd(&g_hist[b*NBIN+i], h[i]);
}

// ---------------- K2: per-image threshold from histogram ----------------
__global__ void k_thresh(){
    __shared__ unsigned h0[NBIN], h1[NBIN];
    int b = blockIdx.x, tid = threadIdx.x;
    for (int i=tid;i<NBIN;i+=1024) h0[i] = g_hist[b*NBIN+i];
    __syncthreads();
    unsigned *src=h0, *dst=h1;
    for (int off=1; off<NBIN; off<<=1){
        for (int i=tid;i<NBIN;i+=1024)
            dst[i] = src[i] + ((i+off<NBIN)? src[i+off] : 0u);
        __syncthreads();
        unsigned* t = src; src = dst; dst = t;
    }
    // src[i] = count of keys >= binStart(i); pick max i with src[i] >= PRE
    for (int i=tid;i<NBIN;i+=1024){
        unsigned si = src[i];
        unsigned nx = (i+1<NBIN)? src[i+1] : 0u;
        if (si >= PRE && nx < PRE) g_thresh[b] = binStartKey((unsigned)i);
    }
}

// ---------------- K3: compact key >= thresh ----------------
__global__ void k_compact(){
    int b = blockIdx.y;
    unsigned K = g_thresh[b];
    const unsigned* keys = g_keys + b*NN;
    int tid = threadIdx.x, lane = tid & 31;
    int start = blockIdx.x*1024 + tid;
    for (int p=start; p<NN; p+=18*1024){
        unsigned key = keys[p];
        bool ok = (key >= K);
        unsigned m = __ballot_sync(0xFFFFFFFFu, ok);
        if (m){
            int leader = __ffs(m)-1;
            int base = 0;
            if (lane==leader) base = atomicAdd(&g_cnt[b], __popc(m));
            base = __shfl_sync(0xFFFFFFFFu, base, leader);
            if (ok){
                int pos = base + __popc(m & ((1u<<lane)-1u));
                if (pos < CAP){
                    int a = p >> 14, rem = p & 16383;
                    int y = rem >> 7, x = rem & 127;
                    unsigned refidx = (unsigned)((y*WW + x)*AA + a);
                    g_items[b*CAP + pos] =
                        ((unsigned long long)key << 32) | (unsigned)(~refidx);
                }
            }
        }
    }
}

// ---------------- K4: register/shfl bitonic sort (8192, desc) + decode --------
// Thread owns 8 contiguous items [tid*8, tid*8+8). Stages:
//   j<8          : in-register compare-exchange
//   j=8..128     : shfl between lanes (partner lane = lane ^ (j>>3))
//   j>=256       : shared memory passes
__device__ __forceinline__ void bitonic_stage(unsigned long long r[8], int tid,
                                              unsigned k, unsigned jstart){
    for (unsigned j=jstart; j>0; j>>=1){
        if (j >= 8u){
            unsigned lm = j >> 3;
            bool amLow = ((((unsigned)tid) & lm) == 0u);
            #pragma unroll
            for (int c=0;c<8;c++){
                unsigned long long other = __shfl_xor_sync(0xFFFFFFFFu, r[c], lm);
                bool d = ((((unsigned)(tid*8+c)) & k) == 0u);  // desc
                bool takeMax = (d == amLow);
                unsigned long long mx = (r[c] > other) ? r[c] : other;
                unsigned long long mn = (r[c] > other) ? other : r[c];
                r[c] = takeMax ? mx : mn;
            }
        } else {
            #pragma unroll
            for (int c=0;c<8;c++){
                int p = c ^ (int)j;
                if (p > c){
                    bool d = ((((unsigned)(tid*8+c)) & k) == 0u);
                    if ((r[c] < r[p]) == d){
                        unsigned long long t=r[c]; r[c]=r[p]; r[p]=t;
                    }
                }
            }
        }
    }
}

__global__ void k_sort(const float* __restrict__ pred, const float* __restrict__ info){
    extern __shared__ unsigned long long sm[];
    int b = blockIdx.x, tid = threadIdx.x;
    int cnt = g_cnt[b]; if (cnt > CAP) cnt = CAP;
    unsigned long long r[8];
    #pragma unroll
    for (int c=0;c<8;c++){
        int i = tid*8 + c;
        r[c] = (i < cnt) ? g_items[b*CAP + i] : 0ull;
    }
    // k = 2..256 entirely in regs/shfl (no barriers)
    for (unsigned k=2; k<=256u; k<<=1) bitonic_stage(r, tid, k, k>>1);
    // k = 512..8192: smem for j>=256, then regs/shfl
    for (unsigned k=512; k<=(unsigned)CAP; k<<=1){
        #pragma unroll
        for (int c=0;c<8;c++) sm[tid*8+c] = r[c];
        __syncthreads();
        for (unsigned j=k>>1; j>=256u; j>>=1){
            #pragma unroll
            for (int t8=0;t8<8;t8++){
                int t = t8*1024 + tid;
                int ixj = t ^ (int)j;
                if (ixj > t){
                    unsigned long long va = sm[t], vb = sm[ixj];
                    bool d = ((((unsigned)t) & k) == 0u);
                    if ((va < vb) == d){ sm[t]=vb; sm[ixj]=va; }
                }
            }
            __syncthreads();
        }
        #pragma unroll
        for (int c=0;c<8;c++) r[c] = sm[tid*8+c];
        bitonic_stage(r, tid, k, 128u);
    }
    // r = globally sorted desc, ranks tid*8+c. Decode top-6000 candidates.
    float imh = __ldg(&info[b*3+0]);
    float imw = __ldg(&info[b*3+1]);
    unsigned negk = keyOf(-1e30f);
    #pragma unroll
    for (int c=0;c<8;c++){
        int i = tid*8 + c;
        if (i < PRE){
            unsigned key = (unsigned)(r[c] >> 32);
            float4 box = make_float4(0.f,0.f,0.f,0.f);
            if (key > negk){
                unsigned refidx = ~((unsigned)r[c]);
                int a = (int)(refidx % AA);
                int cell = (int)(refidx / AA);
                int x = cell & 127, y = cell >> 7;
                float x1,y1,x2,y2,ws,hs;
                decode_box(pred,b,a,y,x,imh,imw,x1,y1,x2,y2,ws,hs);
                box = make_float4(x1,y1,x2,y2);
            }
            g_cand[b*PRE+i]    = box;
            g_candKey[b*PRE+i] = key;
        }
    }
}

// ---------------- K5: greedy NMS, register-resident flags ----------------
__global__ void k_nms(float* __restrict__ out){
    extern __shared__ float smem[];
    float* sx1 = smem;
    float* sy1 = sx1 + PRE;
    float* sx2 = sy1 + PRE;
    float* sy2 = sx2 + PRE;
    __shared__ int s_keep[POST];
    __shared__ unsigned s_wmin[32];
    __shared__ unsigned s_cur;
    int b = blockIdx.x, tid = threadIdx.x, lane = tid & 31, wid = tid >> 5;
    unsigned negk = keyOf(-1e30f);

    float cx1[6],cy1[6],cx2[6],cy2[6],car[6];
    bool alive[6];
    #pragma unroll
    for (int c=0;c<6;c++){
        int i = tid + c*1024;
        cx1[c]=cy1[c]=cx2[c]=cy2[c]=0.f; car[c]=1.f; alive[c]=false;
        if (i < PRE){
            float4 bx = g_cand[b*PRE+i];
            sx1[i]=bx.x; sy1[i]=bx.y; sx2[i]=bx.z; sy2[i]=bx.w;
            cx1[c]=bx.x; cy1[c]=bx.y; cx2[c]=bx.z; cy2[c]=bx.w;
            car[c]=(bx.z-bx.x+1.0f)*(bx.w-bx.y+1.0f);
            alive[c] = (g_candKey[b*PRE+i] > negk);
        }
    }
    __syncthreads();

    int nk = 0;
    while (true){
        unsigned v = 0xFFFFFFFFu;
        #pragma unroll
        for (int c=0;c<6;c++)
            if (v == 0xFFFFFFFFu && alive[c]) v = (unsigned)(tid + c*1024);
        v = __reduce_min_sync(0xFFFFFFFFu, v);
        if (lane == 0) s_wmin[wid] = v;
        __syncthreads();
        if (tid < 32){
            unsigned v2 = __reduce_min_sync(0xFFFFFFFFu, s_wmin[tid]);
            if (tid == 0){
                s_cur = v2;
                if (v2 != 0xFFFFFFFFu) s_keep[nk] = (int)v2;
            }
        }
        __syncthreads();
        unsigned cur = s_cur;
        if (cur == 0xFFFFFFFFu) break;
        nk++;
        float kx1=sx1[cur], ky1=sy1[cur], kx2=sx2[cur], ky2=sy2[cur];
        float kar = (kx2-kx1+1.0f)*(ky2-ky1+1.0f);
        #pragma unroll
        for (int c=0;c<6;c++){
            float xx1=fmaxf(kx1,cx1[c]), yy1=fmaxf(ky1,cy1[c]);
            float xx2=fminf(kx2,cx2[c]), yy2=fminf(ky2,cy2[c]);
            float iw = fmaxf(xx2-xx1+1.0f,0.0f);
            float ih = fmaxf(yy2-yy1+1.0f,0.0f);
            float inter = iw*ih;
            float iou = inter / fmaxf(kar + car[c] - inter, 1e-6f);
            alive[c] = alive[c] && !(iou > NMS_T);
        }
        if (nk == POST) break;
    }

    if (tid < POST){
        int row = (b*POST + tid)*5;
        float v1=0.f,v2=0.f,v3=0.f,v4=0.f;
        if (tid < nk){
            int j = s_keep[tid];
            v1=sx1[j]; v2=sy1[j]; v3=sx2[j]; v4=sy2[j];
        }
        out[row+0]=(float)b; out[row+1]=v1; out[row+2]=v2; out[row+3]=v3; out[row+4]=v4;
    }
}

// ---------------- launcher ----------------
extern "C" void kernel_launch(void* const* d_in, const int* in_sizes, int n_in,
                              void* d_out, int out_size){
    const float* cls  = (const float*)d_in[0];
    const float* pred = (const float*)d_in[1];
    const float* info = (const float*)d_in[2];
    float* out = (float*)d_out;

    cudaFuncSetAttribute(k_sort, cudaFuncAttributeMaxDynamicSharedMemorySize, CAP*8);
    cudaFuncSetAttribute(k_nms,  cudaFuncAttributeMaxDynamicSharedMemorySize, PRE*4*4);

    k_init<<<BB*NBIN/1024, 1024>>>();
    k_score<<<dim3(NN/8192, BB), 1024>>>(cls, pred, info);
    k_thresh<<<BB, 1024>>>();
    k_compact<<<dim3(18, BB), 1024>>>();
    k_sort<<<BB, 1024, CAP*8>>>(pred, info);
    k_nms<<<BB, 1024, PRE*4*4>>>(out);
}

// round 4
// speedup vs baseline: 1.2791x; 1.1174x over previous
#include <cuda_runtime.h>
#include <math.h>
#include <stdint.h>

#define BB 32
#define AA 9
#define HH 128
#define WW 128
#define NN (AA*HH*WW)      /* 147456 */
#define PRE 6000
#define POST 300
#define CAP 8192
#define TGT 7000           /* raw-score cumcount target: >=PRE slack, <=CAP slack */
#define NMS_T 0.7f
#define NBIN 2048

// Anchors: generate_anchors(16,[.5,1,2],[8,16,32]) — exact integers, verified vs numpy.
__constant__ float c_anch[AA*4] = {
   -84.f, -40.f,  99.f,  55.f,
  -176.f, -88.f, 191.f, 103.f,
  -360.f,-184.f, 375.f, 199.f,
   -56.f, -56.f,  71.f,  71.f,
  -120.f,-120.f, 135.f, 135.f,
  -248.f,-248.f, 263.f, 263.f,
   -36.f, -80.f,  51.f,  95.f,
   -80.f,-168.f,  95.f, 183.f,
  -168.f,-344.f, 183.f, 359.f
};

// ---------------- device scratch ----------------
__device__ int                g_cnt[BB];
__device__ unsigned           g_thresh[BB];
__device__ unsigned           g_hist[BB*NBIN];
__device__ unsigned long long g_items[BB*CAP];
__device__ float4             g_cand[BB*PRE];
__device__ unsigned           g_candKey[BB*PRE];

__device__ __forceinline__ unsigned keyOf(float f){
    unsigned u = __float_as_uint(f);
    return (u & 0x80000000u) ? ~u : (u | 0x80000000u);
}

__device__ __forceinline__ void decode_box(const float* __restrict__ pred,
                                           int b, int a, int y, int x,
                                           float imh, float imw,
                                           float& x1, float& y1, float& x2, float& y2,
                                           float& ws, float& hs){
    float sx = (float)(x*16), sy = (float)(y*16);
    float a0 = c_anch[a*4+0]+sx, a1 = c_anch[a*4+1]+sy;
    float a2 = c_anch[a*4+2]+sx, a3 = c_anch[a*4+3]+sy;
    float aw = a2-a0+1.0f, ah = a3-a1+1.0f;
    float cx = a0+0.5f*aw,  cy = a1+0.5f*ah;
    int base = ((b*4*AA + 4*a)*HH + y)*WW + x;
    float dx = pred[base];
    float dy = pred[base +   HH*WW];
    float dw = pred[base + 2*HH*WW];
    float dh = pred[base + 3*HH*WW];
    float pcx = dx*aw+cx, pcy = dy*ah+cy;
    float pw = expf(dw)*aw, ph = expf(dh)*ah;
    x1 = pcx-0.5f*pw; y1 = pcy-0.5f*ph; x2 = pcx+0.5f*pw; y2 = pcy+0.5f*ph;
    x1 = fminf(fmaxf(x1,0.0f), imw-1.0f);
    y1 = fminf(fmaxf(y1,0.0f), imh-1.0f);
    x2 = fminf(fmaxf(x2,0.0f), imw-1.0f);
    y2 = fminf(fmaxf(y2,0.0f), imh-1.0f);
    ws = x2-x1+1.0f; hs = y2-y1+1.0f;
}

// key -> bin (monotone). Fine bins (13-bit key granularity) over key >= keyOf(0.5).
__device__ __forceinline__ unsigned binOf(unsigned key){
    if (key >= 0xBF000000u){
        unsigned b = 1024u + ((key - 0xBF000000u) >> 13);
        return b > 2047u ? 2047u : b;
    }
    unsigned b = key >> 22;
    return b > 1023u ? 1023u : b;
}
__device__ __forceinline__ unsigned binStartKey(unsigned t){
    return (t >= 1024u) ? (0xBF000000u + ((t - 1024u) << 13)) : (t << 22);
}

// ---------------- K0: zero hist + counters ----------------
__global__ void k_init(){
    int i = blockIdx.x*blockDim.x + threadIdx.x;
    if (i < BB*NBIN) g_hist[i] = 0u;
    if (i < BB) g_cnt[i] = 0;
}

// ---------------- K1: raw-score histogram (cls only, no decode) ----------------
__global__ void k_hist(const float* __restrict__ cls){
    __shared__ unsigned h[NBIN];
    int b = blockIdx.y, tid = threadIdx.x;
    const float4* sp = (const float4*)(cls + ((size_t)b*2*AA + AA)*HH*WW);
    for (int i=tid;i<NBIN;i+=1024) h[i]=0u;
    __syncthreads();
    #pragma unroll
    for (int i=0;i<4;i++){
        int f = (blockIdx.x*4 + i)*1024 + tid;     // float4 index in image slab
        float4 v = sp[f];
        atomicAdd(&h[binOf(keyOf(v.x))], 1u);
        atomicAdd(&h[binOf(keyOf(v.y))], 1u);
        atomicAdd(&h[binOf(keyOf(v.z))], 1u);
        atomicAdd(&h[binOf(keyOf(v.w))], 1u);
    }
    __syncthreads();
    for (int i=tid;i<NBIN;i+=1024)
        if (h[i]) atomicAdd(&g_hist[b*NBIN+i], h[i]);
}

// ---------------- K2: threshold = max bin boundary with cumcount >= TGT --------
__global__ void k_thresh(){
    __shared__ unsigned h0[NBIN], h1[NBIN];
    int b = blockIdx.x, tid = threadIdx.x;
    for (int i=tid;i<NBIN;i+=1024) h0[i] = g_hist[b*NBIN+i];
    __syncthreads();
    unsigned *src=h0, *dst=h1;
    for (int off=1; off<NBIN; off<<=1){
        for (int i=tid;i<NBIN;i+=1024)
            dst[i] = src[i] + ((i+off<NBIN)? src[i+off] : 0u);
        __syncthreads();
        unsigned* t = src; src = dst; dst = t;
    }
    for (int i=tid;i<NBIN;i+=1024){
        unsigned si = src[i];
        unsigned nx = (i+1<NBIN)? src[i+1] : 0u;
        if (si >= TGT && nx < TGT) g_thresh[b] = binStartKey((unsigned)i);
    }
}

// ---------------- K3: compact raw>=t0, decode+filter survivors only ------------
__global__ void k_compact(const float* __restrict__ cls, const float* __restrict__ pred,
                          const float* __restrict__ info){
    __shared__ int s_wbase[32];
    __shared__ int s_gbase;
    int b = blockIdx.y, tid = threadIdx.x, lane = tid & 31, wid = tid >> 5;
    unsigned K = g_thresh[b];
    const float4* sp = (const float4*)(cls + ((size_t)b*2*AA + AA)*HH*WW);
    float imh = __ldg(&info[b*3+0]);
    float imw = __ldg(&info[b*3+1]);
    float minsz = 16.0f*__ldg(&info[b*3+2]);

    float s[16];
    unsigned okbits = 0u;
    #pragma unroll
    for (int i=0;i<4;i++){
        int f = (blockIdx.x*4 + i)*1024 + tid;
        float4 v = sp[f];
        s[i*4+0]=v.x; s[i*4+1]=v.y; s[i*4+2]=v.z; s[i*4+3]=v.w;
        if (keyOf(v.x) >= K) okbits |= 1u << (i*4+0);
        if (keyOf(v.y) >= K) okbits |= 1u << (i*4+1);
        if (keyOf(v.z) >= K) okbits |= 1u << (i*4+2);
        if (keyOf(v.w) >= K) okbits |= 1u << (i*4+3);
    }
    int wtot = __reduce_add_sync(0xFFFFFFFFu, __popc(okbits));
    if (lane==0) s_wbase[wid] = wtot;
    __syncthreads();
    if (tid==0){
        int run = 0;
        #pragma unroll
        for (int w=0;w<32;w++){ int t = s_wbase[w]; s_wbase[w] = run; run += t; }
        s_gbase = atomicAdd(&g_cnt[b], run);
    }
    __syncthreads();
    int base = s_gbase + s_wbase[wid];
    #pragma unroll
    for (int sl=0; sl<16; sl++){
        bool ok = (okbits >> sl) & 1u;
        unsigned m = __ballot_sync(0xFFFFFFFFu, ok);
        if (ok){
            int pos = base + __popc(m & ((1u<<lane)-1u));
            if (pos < CAP){
                int i = sl >> 2, c = sl & 3;
                int f = (blockIdx.x*4 + i)*1024 + tid;
                int e = f*4 + c;
                int a = e >> 14, rem = e & 16383;
                int y = rem >> 7, x = rem & 127;
                float x1,y1,x2,y2,ws,hs;
                decode_box(pred,b,a,y,x,imh,imw,x1,y1,x2,y2,ws,hs);
                unsigned key = keyOf(s[sl]);
                if (!(ws >= minsz && hs >= minsz)) key = keyOf(-1e30f);
                unsigned refidx = (unsigned)((y*WW + x)*AA + a);
                g_items[b*CAP + pos] =
                    ((unsigned long long)key << 32) | (unsigned)(~refidx);
            }
        }
        base += __popc(m);
    }
}

// ---------------- K4: register/shfl bitonic sort (8192, desc) + decode --------
__device__ __forceinline__ void bitonic_stage(unsigned long long r[8], int tid,
                                              unsigned k, unsigned jstart){
    for (unsigned j=jstart; j>0; j>>=1){
        if (j >= 8u){
            unsigned lm = j >> 3;
            bool amLow = ((((unsigned)tid) & lm) == 0u);
            #pragma unroll
            for (int c=0;c<8;c++){
                unsigned long long other = __shfl_xor_sync(0xFFFFFFFFu, r[c], lm);
                bool d = ((((unsigned)(tid*8+c)) & k) == 0u);  // desc
                bool takeMax = (d == amLow);
                unsigned long long mx = (r[c] > other) ? r[c] : other;
                unsigned long long mn = (r[c] > other) ? other : r[c];
                r[c] = takeMax ? mx : mn;
            }
        } else {
            #pragma unroll
            for (int c=0;c<8;c++){
                int p = c ^ (int)j;
                if (p > c){
                    bool d = ((((unsigned)(tid*8+c)) & k) == 0u);
                    if ((r[c] < r[p]) == d){
                        unsigned long long t=r[c]; r[c]=r[p]; r[p]=t;
                    }
                }
            }
        }
    }
}

__global__ void k_sort(const float* __restrict__ pred, const float* __restrict__ info){
    extern __shared__ unsigned long long sm[];
    int b = blockIdx.x, tid = threadIdx.x;
    int cnt = g_cnt[b]; if (cnt > CAP) cnt = CAP;
    unsigned long long r[8];
    #pragma unroll
    for (int c=0;c<8;c++){
        int i = tid*8 + c;
        r[c] = (i < cnt) ? g_items[b*CAP + i] : 0ull;
    }
    for (unsigned k=2; k<=256u; k<<=1) bitonic_stage(r, tid, k, k>>1);
    for (unsigned k=512; k<=(unsigned)CAP; k<<=1){
        #pragma unroll
        for (int c=0;c<8;c++) sm[tid*8+c] = r[c];
        __syncthreads();
        for (unsigned j=k>>1; j>=256u; j>>=1){
            #pragma unroll
            for (int t8=0;t8<8;t8++){
                int t = t8*1024 + tid;
                int ixj = t ^ (int)j;
                if (ixj > t){
                    unsigned long long va = sm[t], vb = sm[ixj];
                    bool d = ((((unsigned)t) & k) == 0u);
                    if ((va < vb) == d){ sm[t]=vb; sm[ixj]=va; }
                }
            }
            __syncthreads();
        }
        #pragma unroll
        for (int c=0;c<8;c++) r[c] = sm[tid*8+c];
        bitonic_stage(r, tid, k, 128u);
    }
    float imh = __ldg(&info[b*3+0]);
    float imw = __ldg(&info[b*3+1]);
    unsigned negk = keyOf(-1e30f);
    #pragma unroll
    for (int c=0;c<8;c++){
        int i = tid*8 + c;
        if (i < PRE){
            unsigned key = (unsigned)(r[c] >> 32);
            float4 box = make_float4(0.f,0.f,0.f,0.f);
            if (key > negk){
                unsigned refidx = ~((unsigned)r[c]);
                int a = (int)(refidx % AA);
                int cell = (int)(refidx / AA);
                int x = cell & 127, y = cell >> 7;
                float x1,y1,x2,y2,ws,hs;
                decode_box(pred,b,a,y,x,imh,imw,x1,y1,x2,y2,ws,hs);
                box = make_float4(x1,y1,x2,y2);
            }
            g_cand[b*PRE+i]    = box;
            g_candKey[b*PRE+i] = key;
        }
    }
}

// ---------------- K5: greedy NMS, 1 barrier/iter, register flags ----------------
__global__ void k_nms(float* __restrict__ out){
    extern __shared__ float smem[];
    float* sx1 = smem;
    float* sy1 = sx1 + PRE;
    float* sx2 = sy1 + PRE;
    float* sy2 = sx2 + PRE;
    __shared__ int s_keep[POST];
    __shared__ unsigned s_wmin[2][32];
    int b = blockIdx.x, tid = threadIdx.x, lane = tid & 31, wid = tid >> 5;
    unsigned negk = keyOf(-1e30f);

    float cx1[6],cy1[6],cx2[6],cy2[6],car[6];
    bool alive[6];
    #pragma unroll
    for (int c=0;c<6;c++){
        int i = tid + c*1024;
        cx1[c]=cy1[c]=cx2[c]=cy2[c]=0.f; car[c]=1.f; alive[c]=false;
        if (i < PRE){
            float4 bx = g_cand[b*PRE+i];
            sx1[i]=bx.x; sy1[i]=bx.y; sx2[i]=bx.z; sy2[i]=bx.w;
            cx1[c]=bx.x; cy1[c]=bx.y; cx2[c]=bx.z; cy2[c]=bx.w;
            car[c]=(bx.z-bx.x+1.0f)*(bx.w-bx.y+1.0f);
            alive[c] = (g_candKey[b*PRE+i] > negk);
        }
    }
    __syncthreads();

    int nk = 0, it = 0;
    while (true){
        unsigned v = 0xFFFFFFFFu;
        #pragma unroll
        for (int c=0;c<6;c++)
            if (alive[c]){ unsigned idx = (unsigned)(tid + c*1024); v = (idx<v)?idx:v; }
        v = __reduce_min_sync(0xFFFFFFFFu, v);
        if (lane == 0) s_wmin[it&1][wid] = v;
        __syncthreads();
        unsigned cur = __reduce_min_sync(0xFFFFFFFFu, s_wmin[it&1][lane]);
        it++;
        if (cur == 0xFFFFFFFFu) break;
        if (tid == 0) s_keep[nk] = (int)cur;
        nk++;
        float kx1=sx1[cur], ky1=sy1[cur], kx2=sx2[cur], ky2=sy2[cur];
        float kar = (kx2-kx1+1.0f)*(ky2-ky1+1.0f);
        #pragma unroll
        for (int c=0;c<6;c++){
            float xx1=fmaxf(kx1,cx1[c]), yy1=fmaxf(ky1,cy1[c]);
            float xx2=fminf(kx2,cx2[c]), yy2=fminf(ky2,cy2[c]);
            float iw = fmaxf(xx2-xx1+1.0f,0.0f);
            float ih = fmaxf(yy2-yy1+1.0f,0.0f);
            float inter = iw*ih;
            float iou = inter / fmaxf(kar + car[c] - inter, 1e-6f);
            alive[c] = alive[c] && !(iou > NMS_T);
        }
        if (nk == POST) break;
    }
    __syncthreads();

    if (tid < POST){
        int row = (b*POST + tid)*5;
        float v1=0.f,v2=0.f,v3=0.f,v4=0.f;
        if (tid < nk){
            int j = s_keep[tid];
            v1=sx1[j]; v2=sy1[j]; v3=sx2[j]; v4=sy2[j];
        }
        out[row+0]=(float)b; out[row+1]=v1; out[row+2]=v2; out[row+3]=v3; out[row+4]=v4;
    }
}

// ---------------- launcher ----------------
extern "C" void kernel_launch(void* const* d_in, const int* in_sizes, int n_in,
                              void* d_out, int out_size){
    const float* cls  = (const float*)d_in[0];
    const float* pred = (const float*)d_in[1];
    const float* info = (const float*)d_in[2];
    float* out = (float*)d_out;

    cudaFuncSetAttribute(k_sort, cudaFuncAttributeMaxDynamicSharedMemorySize, CAP*8);
    cudaFuncSetAttribute(k_nms,  cudaFuncAttributeMaxDynamicSharedMemorySize, PRE*4*4);

    k_init<<<BB*NBIN/1024, 1024>>>();
    k_hist<<<dim3(9, BB), 1024>>>(cls);
    k_thresh<<<BB, 1024>>>();
    k_compact<<<dim3(9, BB), 1024>>>(cls, pred, info);
    k_sort<<<BB, 1024, CAP*8>>>(pred, info);
    k_nms<<<BB, 1024, PRE*4*4>>>(out);
}

// round 6
// speedup vs baseline: 1.3590x; 1.0625x over previous
#include <cuda_runtime.h>
#include <math.h>
#include <stdint.h>

#define BB 32
#define AA 9
#define HH 128
#define WW 128
#define NN (AA*HH*WW)      /* 147456 */
#define PRE 6000
#define POST 300
#define CAP 8192
#define TGT 7000           /* raw-score cumcount target: >=PRE slack, <=CAP slack */
#define NMS_T 0.7f
#define NBIN 2048

// Anchors: generate_anchors(16,[.5,1,2],[8,16,32]) — exact integers, verified vs numpy.
__constant__ float c_anch[AA*4] = {
   -84.f, -40.f,  99.f,  55.f,
  -176.f, -88.f, 191.f, 103.f,
  -360.f,-184.f, 375.f, 199.f,
   -56.f, -56.f,  71.f,  71.f,
  -120.f,-120.f, 135.f, 135.f,
  -248.f,-248.f, 263.f, 263.f,
   -36.f, -80.f,  51.f,  95.f,
   -80.f,-168.f,  95.f, 183.f,
  -168.f,-344.f, 183.f, 359.f
};

// ---------------- device scratch ----------------
__device__ int                g_cnt[BB];
__device__ unsigned           g_thresh[BB];
__device__ unsigned           g_hist[BB*NBIN];
__device__ unsigned long long g_items[BB*CAP];
__device__ float4             g_cand[BB*PRE];
__device__ unsigned           g_candKey[BB*PRE];

__device__ __forceinline__ unsigned keyOf(float f){
    unsigned u = __float_as_uint(f);
    return (u & 0x80000000u) ? ~u : (u | 0x80000000u);
}

__device__ __forceinline__ void decode_box(const float* __restrict__ pred,
                                           int b, int a, int y, int x,
                                           float imh, float imw,
                                           float& x1, float& y1, float& x2, float& y2,
                                           float& ws, float& hs){
    float sx = (float)(x*16), sy = (float)(y*16);
    float a0 = c_anch[a*4+0]+sx, a1 = c_anch[a*4+1]+sy;
    float a2 = c_anch[a*4+2]+sx, a3 = c_anch[a*4+3]+sy;
    float aw = a2-a0+1.0f, ah = a3-a1+1.0f;
    float cx = a0+0.5f*aw,  cy = a1+0.5f*ah;
    int base = ((b*4*AA + 4*a)*HH + y)*WW + x;
    float dx = pred[base];
    float dy = pred[base +   HH*WW];
    float dw = pred[base + 2*HH*WW];
    float dh = pred[base + 3*HH*WW];
    float pcx = dx*aw+cx, pcy = dy*ah+cy;
    float pw = expf(dw)*aw, ph = expf(dh)*ah;
    x1 = pcx-0.5f*pw; y1 = pcy-0.5f*ph; x2 = pcx+0.5f*pw; y2 = pcy+0.5f*ph;
    x1 = fminf(fmaxf(x1,0.0f), imw-1.0f);
    y1 = fminf(fmaxf(y1,0.0f), imh-1.0f);
    x2 = fminf(fmaxf(x2,0.0f), imw-1.0f);
    y2 = fminf(fmaxf(y2,0.0f), imh-1.0f);
    ws = x2-x1+1.0f; hs = y2-y1+1.0f;
}

// key -> bin (monotone). Fine bins (13-bit key granularity) over key >= keyOf(0.5).
__device__ __forceinline__ unsigned binOf(unsigned key){
    if (key >= 0xBF000000u){
        unsigned b = 1024u + ((key - 0xBF000000u) >> 13);
        return b > 2047u ? 2047u : b;
    }
    unsigned b = key >> 22;
    return b > 1023u ? 1023u : b;
}
__device__ __forceinline__ unsigned binStartKey(unsigned t){
    return (t >= 1024u) ? (0xBF000000u + ((t - 1024u) << 13)) : (t << 22);
}

// ---------------- K0: zero hist + counters ----------------
__global__ void k_init(){
    int i = blockIdx.x*blockDim.x + threadIdx.x;
    if (i < BB*NBIN) g_hist[i] = 0u;
    if (i < BB) g_cnt[i] = 0;
}

// ---------------- K1: raw-score histogram (cls only, no decode) ----------------
__global__ void k_hist(const float* __restrict__ cls){
    __shared__ unsigned h[NBIN];
    int b = blockIdx.y, tid = threadIdx.x;
    const float4* sp = (const float4*)(cls + ((size_t)b*2*AA + AA)*HH*WW);
    for (int i=tid;i<NBIN;i+=1024) h[i]=0u;
    __syncthreads();
    #pragma unroll
    for (int i=0;i<4;i++){
        int f = (blockIdx.x*4 + i)*1024 + tid;     // float4 index in image slab
        float4 v = sp[f];
        atomicAdd(&h[binOf(keyOf(v.x))], 1u);
        atomicAdd(&h[binOf(keyOf(v.y))], 1u);
        atomicAdd(&h[binOf(keyOf(v.z))], 1u);
        atomicAdd(&h[binOf(keyOf(v.w))], 1u);
    }
    __syncthreads();
    for (int i=tid;i<NBIN;i+=1024)
        if (h[i]) atomicAdd(&g_hist[b*NBIN+i], h[i]);
}

// ---------------- K2: threshold = max bin boundary with cumcount >= TGT --------
__global__ void k_thresh(){
    __shared__ unsigned h0[NBIN], h1[NBIN];
    int b = blockIdx.x, tid = threadIdx.x;
    for (int i=tid;i<NBIN;i+=1024) h0[i] = g_hist[b*NBIN+i];
    __syncthreads();
    unsigned *src=h0, *dst=h1;
    for (int off=1; off<NBIN; off<<=1){
        for (int i=tid;i<NBIN;i+=1024)
            dst[i] = src[i] + ((i+off<NBIN)? src[i+off] : 0u);
        __syncthreads();
        unsigned* t = src; src = dst; dst = t;
    }
    for (int i=tid;i<NBIN;i+=1024){
        unsigned si = src[i];
        unsigned nx = (i+1<NBIN)? src[i+1] : 0u;
        if (si >= TGT && nx < TGT) g_thresh[b] = binStartKey((unsigned)i);
    }
}

// ---------------- K3: compact raw>=t0, decode+filter survivors only ------------
__global__ void k_compact(const float* __restrict__ cls, const float* __restrict__ pred,
                          const float* __restrict__ info){
    __shared__ int s_wbase[32];
    __shared__ int s_gbase;
    int b = blockIdx.y, tid = threadIdx.x, lane = tid & 31, wid = tid >> 5;
    unsigned K = g_thresh[b];
    const float4* sp = (const float4*)(cls + ((size_t)b*2*AA + AA)*HH*WW);
    float imh = __ldg(&info[b*3+0]);
    float imw = __ldg(&info[b*3+1]);
    float minsz = 16.0f*__ldg(&info[b*3+2]);

    float s[16];
    unsigned okbits = 0u;
    #pragma unroll
    for (int i=0;i<4;i++){
        int f = (blockIdx.x*4 + i)*1024 + tid;
        float4 v = sp[f];
        s[i*4+0]=v.x; s[i*4+1]=v.y; s[i*4+2]=v.z; s[i*4+3]=v.w;
        if (keyOf(v.x) >= K) okbits |= 1u << (i*4+0);
        if (keyOf(v.y) >= K) okbits |= 1u << (i*4+1);
        if (keyOf(v.z) >= K) okbits |= 1u << (i*4+2);
        if (keyOf(v.w) >= K) okbits |= 1u << (i*4+3);
    }
    int wtot = __reduce_add_sync(0xFFFFFFFFu, __popc(okbits));
    if (lane==0) s_wbase[wid] = wtot;
    __syncthreads();
    if (tid==0){
        int run = 0;
        #pragma unroll
        for (int w=0;w<32;w++){ int t = s_wbase[w]; s_wbase[w] = run; run += t; }
        s_gbase = atomicAdd(&g_cnt[b], run);
    }
    __syncthreads();
    int base = s_gbase + s_wbase[wid];
    #pragma unroll
    for (int sl=0; sl<16; sl++){
        bool ok = (okbits >> sl) & 1u;
        unsigned m = __ballot_sync(0xFFFFFFFFu, ok);
        if (ok){
            int pos = base + __popc(m & ((1u<<lane)-1u));
            if (pos < CAP){
                int i = sl >> 2, c = sl & 3;
                int f = (blockIdx.x*4 + i)*1024 + tid;
                int e = f*4 + c;
                int a = e >> 14, rem = e & 16383;
                int y = rem >> 7, x = rem & 127;
                float x1,y1,x2,y2,ws,hs;
                decode_box(pred,b,a,y,x,imh,imw,x1,y1,x2,y2,ws,hs);
                unsigned key = keyOf(s[sl]);
                if (!(ws >= minsz && hs >= minsz)) key = keyOf(-1e30f);
                unsigned refidx = (unsigned)((y*WW + x)*AA + a);
                g_items[b*CAP + pos] =
                    ((unsigned long long)key << 32) | (unsigned)(~refidx);
            }
        }
        base += __popc(m);
    }
}

// ---------------- K4: register/shfl bitonic sort (8192, desc) + decode --------
// Thread owns 8 contiguous items [tid*8, tid*8+8). All register-stage indices
// are COMPILE-TIME (template J) so r[] never spills to local memory.
template<unsigned J>
__device__ __forceinline__ void reg_stage(unsigned long long r[8], unsigned tid, unsigned k){
    if constexpr (J >= 8u){
        constexpr unsigned lm = J >> 3;
        bool amLow = ((tid & lm) == 0u);
        #pragma unroll
        for (int c=0;c<8;c++){
            unsigned long long other = __shfl_xor_sync(0xFFFFFFFFu, r[c], lm);
            bool d = (((tid*8u + (unsigned)c) & k) == 0u);  // desc
            bool takeMax = (d == amLow);
            unsigned long long mx = (r[c] > other) ? r[c] : other;
            unsigned long long mn = (r[c] > other) ? other : r[c];
            r[c] = takeMax ? mx : mn;
        }
    } else {
        #pragma unroll
        for (int c=0;c<8;c++){
            constexpr int JJ = (int)J;
            int p = c ^ JJ;                 // compile-time after unroll
            if (p > c){
                bool d = (((tid*8u + (unsigned)c) & k) == 0u);
                if ((r[c] < r[p]) == d){
                    unsigned long long t=r[c]; r[c]=r[p]; r[p]=t;
                }
            }
        }
    }
    if constexpr (J > 1u) reg_stage<J/2u>(r, tid, k);
}

__global__ void __launch_bounds__(1024,1)
k_sort(const float* __restrict__ pred, const float* __restrict__ info){
    extern __shared__ unsigned long long sm[];
    int b = blockIdx.x;
    unsigned tid = threadIdx.x;
    int cnt = g_cnt[b]; if (cnt > CAP) cnt = CAP;
    unsigned long long r[8];
    #pragma unroll
    for (int c=0;c<8;c++){
        int i = (int)tid*8 + c;
        r[c] = (i < cnt) ? g_items[b*CAP + i] : 0ull;
    }
    // k = 2..256 entirely in regs/shfl, fully static indexing, no barriers
    reg_stage<1u>(r, tid, 2u);
    reg_stage<2u>(r, tid, 4u);
    reg_stage<4u>(r, tid, 8u);
    reg_stage<8u>(r, tid, 16u);
    reg_stage<16u>(r, tid, 32u);
    reg_stage<32u>(r, tid, 64u);
    reg_stage<64u>(r, tid, 128u);
    reg_stage<128u>(r, tid, 256u);
    // k = 512..8192: smem for j>=256, then static register stages
    for (unsigned k=512u; k<=(unsigned)CAP; k<<=1){
        #pragma unroll
        for (int c=0;c<8;c++) sm[tid*8u+c] = r[c];
        __syncthreads();
        for (unsigned j=k>>1; j>=256u; j>>=1){
            // enumerate only active pairs: 4096 pairs, 4 per thread
            #pragma unroll
            for (int q4=0; q4<4; q4++){
                unsigned q = (unsigned)q4*1024u + tid;
                unsigned t = ((q & ~(j-1u)) << 1) | (q & (j-1u));
                unsigned ixj = t | j;
                unsigned long long va = sm[t], vb = sm[ixj];
                bool d = ((t & k) == 0u);
                if ((va < vb) == d){ sm[t]=vb; sm[ixj]=va; }
            }
            __syncthreads();
        }
        #pragma unroll
        for (int c=0;c<8;c++) r[c] = sm[tid*8u+c];
        reg_stage<128u>(r, tid, k);
    }
    // r = globally sorted desc, ranks tid*8+c. Decode top-6000 candidates.
    float imh = __ldg(&info[b*3+0]);
    float imw = __ldg(&info[b*3+1]);
    unsigned negk = keyOf(-1e30f);
    #pragma unroll
    for (int c=0;c<8;c++){
        int i = (int)tid*8 + c;
        if (i < PRE){
            unsigned key = (unsigned)(r[c] >> 32);
            float4 box = make_float4(0.f,0.f,0.f,0.f);
            if (key > negk){
                unsigned refidx = ~((unsigned)r[c]);
                int a = (int)(refidx % AA);
                int cell = (int)(refidx / AA);
                int x = cell & 127, y = cell >> 7;
                float x1,y1,x2,y2,ws,hs;
                decode_box(pred,b,a,y,x,imh,imw,x1,y1,x2,y2,ws,hs);
                box = make_float4(x1,y1,x2,y2);
            }
            g_cand[b*PRE+i]    = box;
            g_candKey[b*PRE+i] = key;
        }
    }
}

// ---------------- K5: greedy NMS, 1 barrier/iter, register flags ----------------
__global__ void k_nms(float* __restrict__ out){
    extern __shared__ float smem[];
    float* sx1 = smem;
    float* sy1 = sx1 + PRE;
    float* sx2 = sy1 + PRE;
    float* sy2 = sx2 + PRE;
    __shared__ int s_keep[POST];
    __shared__ unsigned s_wmin[2][32];
    int b = blockIdx.x, tid = threadIdx.x, lane = tid & 31, wid = tid >> 5;
    unsigned negk = keyOf(-1e30f);

    float cx1[6],cy1[6],cx2[6],cy2[6],car[6];
    bool alive[6];
    #pragma unroll
    for (int c=0;c<6;c++){
        int i = tid + c*1024;
        cx1[c]=cy1[c]=cx2[c]=cy2[c]=0.f; car[c]=1.f; alive[c]=false;
        if (i < PRE){
            float4 bx = g_cand[b*PRE+i];
            sx1[i]=bx.x; sy1[i]=bx.y; sx2[i]=bx.z; sy2[i]=bx.w;
            cx1[c]=bx.x; cy1[c]=bx.y; cx2[c]=bx.z; cy2[c]=bx.w;
            car[c]=(bx.z-bx.x+1.0f)*(bx.w-bx.y+1.0f);
            alive[c] = (g_candKey[b*PRE+i] > negk);
        }
    }
    __syncthreads();

    int nk = 0, it = 0;
    while (true){
        unsigned v = 0xFFFFFFFFu;
        #pragma unroll
        for (int c=0;c<6;c++)
            if (alive[c]){ unsigned idx = (unsigned)(tid + c*1024); v = (idx<v)?idx:v; }
        v = __reduce_min_sync(0xFFFFFFFFu, v);
        if (lane == 0) s_wmin[it&1][wid] = v;
        __syncthreads();
        unsigned cur = __reduce_min_sync(0xFFFFFFFFu, s_wmin[it&1][lane]);
        it++;
        if (cur == 0xFFFFFFFFu) break;
        if (tid == 0) s_keep[nk] = (int)cur;
        nk++;
        float kx1=sx1[cur], ky1=sy1[cur], kx2=sx2[cur], ky2=sy2[cur];
        float kar = (kx2-kx1+1.0f)*(ky2-ky1+1.0f);
        #pragma unroll
        for (int c=0;c<6;c++){
            float xx1=fmaxf(kx1,cx1[c]), yy1=fmaxf(ky1,cy1[c]);
            float xx2=fminf(kx2,cx2[c]), yy2=fminf(ky2,cy2[c]);
            float iw = fmaxf(xx2-xx1+1.0f,0.0f);
            float ih = fmaxf(yy2-yy1+1.0f,0.0f);
            float inter = iw*ih;
            float iou = inter / fmaxf(kar + car[c] - inter, 1e-6f);
            alive[c] = alive[c] && !(iou > NMS_T);
        }
        if (nk == POST) break;
    }
    __syncthreads();

    if (tid < POST){
        int row = (b*POST + tid)*5;
        float v1=0.f,v2=0.f,v3=0.f,v4=0.f;
        if (tid < nk){
            int j = s_keep[tid];
            v1=sx1[j]; v2=sy1[j]; v3=sx2[j]; v4=sy2[j];
        }
        out[row+0]=(float)b; out[row+1]=v1; out[row+2]=v2; out[row+3]=v3; out[row+4]=v4;
    }
}

// ---------------- launcher ----------------
extern "C" void kernel_launch(void* const* d_in, const int* in_sizes, int n_in,
                              void* d_out, int out_size){
    const float* cls  = (const float*)d_in[0];
    const float* pred = (const float*)d_in[1];
    const float* info = (const float*)d_in[2];
    float* out = (float*)d_out;

    cudaFuncSetAttribute(k_sort, cudaFuncAttributeMaxDynamicSharedMemorySize, CAP*8);
    cudaFuncSetAttribute(k_nms,  cudaFuncAttributeMaxDynamicSharedMemorySize, PRE*4*4);

    k_init<<<BB*NBIN/1024, 1024>>>();
    k_hist<<<dim3(9, BB), 1024>>>(cls);
    k_thresh<<<BB, 1024>>>();
    k_compact<<<dim3(9, BB), 1024>>>(cls, pred, info);
    k_sort<<<BB, 1024, CAP*8>>>(pred, info);
    k_nms<<<BB, 1024, PRE*4*4>>>(out);
}

// round 8
// speedup vs baseline: 4.8814x; 3.5918x over previous
#include <cuda_runtime.h>
#include <math.h>
#include <stdint.h>

#define BB 32
#define AA 9
#define HH 128
#define WW 128
#define NN (AA*HH*WW)      /* 147456 */
#define PRE 6000
#define POST 300
#define CAP 8192
#define TGT 7000           /* raw-score cumcount target: >=PRE slack, <=CAP slack */
#define NMS_T 0.7f
#define NBIN 2048

// Anchors: generate_anchors(16,[.5,1,2],[8,16,32]) — exact integers, verified vs numpy.
__constant__ float c_anch[AA*4] = {
   -84.f, -40.f,  99.f,  55.f,
  -176.f, -88.f, 191.f, 103.f,
  -360.f,-184.f, 375.f, 199.f,
   -56.f, -56.f,  71.f,  71.f,
  -120.f,-120.f, 135.f, 135.f,
  -248.f,-248.f, 263.f, 263.f,
   -36.f, -80.f,  51.f,  95.f,
   -80.f,-168.f,  95.f, 183.f,
  -168.f,-344.f, 183.f, 359.f
};

// ---------------- device scratch ----------------
__device__ int                g_cnt[BB];
__device__ unsigned           g_thresh[BB];
__device__ unsigned           g_hist[BB*NBIN];
__device__ unsigned long long g_items[BB*CAP];
__device__ float4             g_cand[BB*PRE];
__device__ unsigned           g_candKey[BB*PRE];

__device__ __forceinline__ unsigned keyOf(float f){
    unsigned u = __float_as_uint(f);
    return (u & 0x80000000u) ? ~u : (u | 0x80000000u);
}

__device__ __forceinline__ void decode_box(const float* __restrict__ pred,
                                           int b, int a, int y, int x,
                                           float imh, float imw,
                                           float& x1, float& y1, float& x2, float& y2,
                                           float& ws, float& hs){
    float sx = (float)(x*16), sy = (float)(y*16);
    float a0 = c_anch[a*4+0]+sx, a1 = c_anch[a*4+1]+sy;
    float a2 = c_anch[a*4+2]+sx, a3 = c_anch[a*4+3]+sy;
    float aw = a2-a0+1.0f, ah = a3-a1+1.0f;
    float cx = a0+0.5f*aw,  cy = a1+0.5f*ah;
    int base = ((b*4*AA + 4*a)*HH + y)*WW + x;
    float dx = pred[base];
    float dy = pred[base +   HH*WW];
    float dw = pred[base + 2*HH*WW];
    float dh = pred[base + 3*HH*WW];
    float pcx = dx*aw+cx, pcy = dy*ah+cy;
    float pw = expf(dw)*aw, ph = expf(dh)*ah;
    x1 = pcx-0.5f*pw; y1 = pcy-0.5f*ph; x2 = pcx+0.5f*pw; y2 = pcy+0.5f*ph;
    x1 = fminf(fmaxf(x1,0.0f), imw-1.0f);
    y1 = fminf(fmaxf(y1,0.0f), imh-1.0f);
    x2 = fminf(fmaxf(x2,0.0f), imw-1.0f);
    y2 = fminf(fmaxf(y2,0.0f), imh-1.0f);
    ws = x2-x1+1.0f; hs = y2-y1+1.0f;
}

// key -> bin (monotone). Fine bins (13-bit key granularity) over key >= keyOf(0.5).
__device__ __forceinline__ unsigned binOf(unsigned key){
    if (key >= 0xBF000000u){
        unsigned b = 1024u + ((key - 0xBF000000u) >> 13);
        return b > 2047u ? 2047u : b;
    }
    unsigned b = key >> 22;
    return b > 1023u ? 1023u : b;
}
__device__ __forceinline__ unsigned binStartKey(unsigned t){
    return (t >= 1024u) ? (0xBF000000u + ((t - 1024u) << 13)) : (t << 22);
}

// ---------------- K0: zero hist + counters ----------------
__global__ void k_init(){
    int i = blockIdx.x*blockDim.x + threadIdx.x;
    if (i < BB*NBIN) g_hist[i] = 0u;
    if (i < BB) g_cnt[i] = 0;
}

// ---------------- K1: raw-score histogram (cls only, no decode) ----------------
__global__ void k_hist(const float* __restrict__ cls){
    __shared__ unsigned h[NBIN];
    int b = blockIdx.y, tid = threadIdx.x;
    const float4* sp = (const float4*)(cls + ((size_t)b*2*AA + AA)*HH*WW);
    for (int i=tid;i<NBIN;i+=1024) h[i]=0u;
    __syncthreads();
    #pragma unroll
    for (int i=0;i<4;i++){
        int f = (blockIdx.x*4 + i)*1024 + tid;     // float4 index in image slab
        float4 v = sp[f];
        atomicAdd(&h[binOf(keyOf(v.x))], 1u);
        atomicAdd(&h[binOf(keyOf(v.y))], 1u);
        atomicAdd(&h[binOf(keyOf(v.z))], 1u);
        atomicAdd(&h[binOf(keyOf(v.w))], 1u);
    }
    __syncthreads();
    for (int i=tid;i<NBIN;i+=1024)
        if (h[i]) atomicAdd(&g_hist[b*NBIN+i], h[i]);
}

// ---------------- K2: threshold = max bin boundary with cumcount >= TGT --------
__global__ void k_thresh(){
    __shared__ unsigned h0[NBIN], h1[NBIN];
    int b = blockIdx.x, tid = threadIdx.x;
    for (int i=tid;i<NBIN;i+=1024) h0[i] = g_hist[b*NBIN+i];
    __syncthreads();
    unsigned *src=h0, *dst=h1;
    for (int off=1; off<NBIN; off<<=1){
        for (int i=tid;i<NBIN;i+=1024)
            dst[i] = src[i] + ((i+off<NBIN)? src[i+off] : 0u);
        __syncthreads();
        unsigned* t = src; src = dst; dst = t;
    }
    for (int i=tid;i<NBIN;i+=1024){
        unsigned si = src[i];
        unsigned nx = (i+1<NBIN)? src[i+1] : 0u;
        if (si >= TGT && nx < TGT) g_thresh[b] = binStartKey((unsigned)i);
    }
}

// ---------------- K3: compact raw>=t0, decode+filter survivors only ------------
__global__ void k_compact(const float* __restrict__ cls, const float* __restrict__ pred,
                          const float* __restrict__ info){
    __shared__ int s_wbase[32];
    __shared__ int s_gbase;
    int b = blockIdx.y, tid = threadIdx.x, lane = tid & 31, wid = tid >> 5;
    unsigned K = g_thresh[b];
    const float4* sp = (const float4*)(cls + ((size_t)b*2*AA + AA)*HH*WW);
    float imh = __ldg(&info[b*3+0]);
    float imw = __ldg(&info[b*3+1]);
    float minsz = 16.0f*__ldg(&info[b*3+2]);

    float s[16];
    unsigned okbits = 0u;
    #pragma unroll
    for (int i=0;i<4;i++){
        int f = (blockIdx.x*4 + i)*1024 + tid;
        float4 v = sp[f];
        s[i*4+0]=v.x; s[i*4+1]=v.y; s[i*4+2]=v.z; s[i*4+3]=v.w;
        if (keyOf(v.x) >= K) okbits |= 1u << (i*4+0);
        if (keyOf(v.y) >= K) okbits |= 1u << (i*4+1);
        if (keyOf(v.z) >= K) okbits |= 1u << (i*4+2);
        if (keyOf(v.w) >= K) okbits |= 1u << (i*4+3);
    }
    int wtot = __reduce_add_sync(0xFFFFFFFFu, __popc(okbits));
    if (lane==0) s_wbase[wid] = wtot;
    __syncthreads();
    if (tid==0){
        int run = 0;
        #pragma unroll
        for (int w=0;w<32;w++){ int t = s_wbase[w]; s_wbase[w] = run; run += t; }
        s_gbase = atomicAdd(&g_cnt[b], run);
    }
    __syncthreads();
    int base = s_gbase + s_wbase[wid];
    #pragma unroll
    for (int sl=0; sl<16; sl++){
        bool ok = (okbits >> sl) & 1u;
        unsigned m = __ballot_sync(0xFFFFFFFFu, ok);
        if (ok){
            int pos = base + __popc(m & ((1u<<lane)-1u));
            if (pos < CAP){
                int i = sl >> 2, c = sl & 3;
                int f = (blockIdx.x*4 + i)*1024 + tid;
                int e = f*4 + c;
                int a = e >> 14, rem = e & 16383;
                int y = rem >> 7, x = rem & 127;
                float x1,y1,x2,y2,ws,hs;
                decode_box(pred,b,a,y,x,imh,imw,x1,y1,x2,y2,ws,hs);
                unsigned key = keyOf(s[sl]);
                if (!(ws >= minsz && hs >= minsz)) key = keyOf(-1e30f);
                unsigned refidx = (unsigned)((y*WW + x)*AA + a);
                g_items[b*CAP + pos] =
                    ((unsigned long long)key << 32) | (unsigned)(~refidx);
            }
        }
        base += __popc(m);
    }
}

// ---------------- K4: register/shfl bitonic sort (8192, desc) + decode --------
template<unsigned J>
__device__ __forceinline__ void reg_stage(unsigned long long r[8], unsigned tid, unsigned k){
    if constexpr (J >= 8u){
        constexpr unsigned lm = J >> 3;
        bool amLow = ((tid & lm) == 0u);
        #pragma unroll
        for (int c=0;c<8;c++){
            unsigned long long other = __shfl_xor_sync(0xFFFFFFFFu, r[c], lm);
            bool d = (((tid*8u + (unsigned)c) & k) == 0u);  // desc
            bool takeMax = (d == amLow);
            unsigned long long mx = (r[c] > other) ? r[c] : other;
            unsigned long long mn = (r[c] > other) ? other : r[c];
            r[c] = takeMax ? mx : mn;
        }
    } else {
        #pragma unroll
        for (int c=0;c<8;c++){
            constexpr int JJ = (int)J;
            int p = c ^ JJ;                 // compile-time after unroll
            if (p > c){
                bool d = (((tid*8u + (unsigned)c) & k) == 0u);
                if ((r[c] < r[p]) == d){
                    unsigned long long t=r[c]; r[c]=r[p]; r[p]=t;
                }
            }
        }
    }
    if constexpr (J > 1u) reg_stage<J/2u>(r, tid, k);
}

__global__ void __launch_bounds__(1024,1)
k_sort(const float* __restrict__ pred, const float* __restrict__ info){
    extern __shared__ unsigned long long sm[];
    int b = blockIdx.x;
    unsigned tid = threadIdx.x;
    int cnt = g_cnt[b]; if (cnt > CAP) cnt = CAP;
    unsigned long long r[8];
    #pragma unroll
    for (int c=0;c<8;c++){
        int i = (int)tid*8 + c;
        r[c] = (i < cnt) ? g_items[b*CAP + i] : 0ull;
    }
    reg_stage<1u>(r, tid, 2u);
    reg_stage<2u>(r, tid, 4u);
    reg_stage<4u>(r, tid, 8u);
    reg_stage<8u>(r, tid, 16u);
    reg_stage<16u>(r, tid, 32u);
    reg_stage<32u>(r, tid, 64u);
    reg_stage<64u>(r, tid, 128u);
    reg_stage<128u>(r, tid, 256u);
    for (unsigned k=512u; k<=(unsigned)CAP; k<<=1){
        #pragma unroll
        for (int c=0;c<8;c++) sm[tid*8u+c] = r[c];
        __syncthreads();
        for (unsigned j=k>>1; j>=256u; j>>=1){
            #pragma unroll
            for (int q4=0; q4<4; q4++){
                unsigned q = (unsigned)q4*1024u + tid;
                unsigned t = ((q & ~(j-1u)) << 1) | (q & (j-1u));
                unsigned ixj = t | j;
                unsigned long long va = sm[t], vb = sm[ixj];
                bool d = ((t & k) == 0u);
                if ((va < vb) == d){ sm[t]=vb; sm[ixj]=va; }
            }
            __syncthreads();
        }
        #pragma unroll
        for (int c=0;c<8;c++) r[c] = sm[tid*8u+c];
        reg_stage<128u>(r, tid, k);
    }
    float imh = __ldg(&info[b*3+0]);
    float imw = __ldg(&info[b*3+1]);
    unsigned negk = keyOf(-1e30f);
    #pragma unroll
    for (int c=0;c<8;c++){
        int i = (int)tid*8 + c;
        if (i < PRE){
            unsigned key = (unsigned)(r[c] >> 32);
            float4 box = make_float4(0.f,0.f,0.f,0.f);
            if (key > negk){
                unsigned refidx = ~((unsigned)r[c]);
                int a = (int)(refidx % AA);
                int cell = (int)(refidx / AA);
                int x = cell & 127, y = cell >> 7;
                float x1,y1,x2,y2,ws,hs;
                decode_box(pred,b,a,y,x,imh,imw,x1,y1,x2,y2,ws,hs);
                box = make_float4(x1,y1,x2,y2);
            }
            g_cand[b*PRE+i]    = box;
            g_candKey[b*PRE+i] = key;
        }
    }
}

// ---------------- K5: incremental sweep NMS ----------------
// Equivalent formulation of sorted greedy NMS: candidate i is kept iff
// IoU(i, j) <= T for every kept j < i. Processed in 32-candidate chunks:
// phase 1 tests the chunk against all previously kept boxes (striped over
// 16 warps); phase 2 (warp 0) serially resolves intra-chunk keeps.
#define NMST 512
__global__ void __launch_bounds__(NMST,1) k_nms(float* __restrict__ out){
    __shared__ float4   s_kept[POST];
    __shared__ unsigned s_warp[NMST/32];
    __shared__ int      s_nk;
    int b = blockIdx.x, tid = threadIdx.x, lane = tid & 31, wid = tid >> 5;
    unsigned negk = keyOf(-1e30f);
    if (tid == 0) s_nk = 0;
    __syncthreads();

    int nk = 0;
    const int NCHUNK = (PRE + 31) / 32;   // 188
    for (int ch = 0; ch < NCHUNK; ch++){
        int ci = ch*32 + lane;
        float4 bx = make_float4(0.f,0.f,0.f,0.f);
        bool valid = false;
        if (ci < PRE){
            bx = g_cand[b*PRE + ci];
            valid = (g_candKey[b*PRE + ci] > negk);
        }
        float area = (bx.z-bx.x+1.0f)*(bx.w-bx.y+1.0f);
        // phase 1: test my candidate vs kept boxes wid, wid+16, wid+32, ...
        bool sup = !valid;
        for (int j = wid; j < nk; j += NMST/32){
            float4 kb = s_kept[j];
            float ka = (kb.z-kb.x+1.0f)*(kb.w-kb.y+1.0f);
            float xx1=fmaxf(kb.x,bx.x), yy1=fmaxf(kb.y,bx.y);
            float xx2=fminf(kb.z,bx.z), yy2=fminf(kb.w,bx.w);
            float inter = fmaxf(xx2-xx1+1.0f,0.0f)*fmaxf(yy2-yy1+1.0f,0.0f);
            float iou = inter / fmaxf(ka + area - inter, 1e-6f);
            sup = sup | (iou > NMS_T);
        }
        unsigned m = __ballot_sync(0xFFFFFFFFu, sup);
        if (lane == 0) s_warp[wid] = m;
        __syncthreads();
        // phase 2: warp 0 resolves the chunk serially
        if (wid == 0){
            unsigned v = (lane < NMST/32) ? s_warp[lane] : 0u;
            unsigned supmask = __reduce_or_sync(0xFFFFFFFFu, v);
            unsigned alivemask = ~supmask;
            while (alivemask && nk < POST){
                int bp = __ffs(alivemask) - 1;
                float kx1 = __shfl_sync(0xFFFFFFFFu, bx.x, bp);
                float ky1 = __shfl_sync(0xFFFFFFFFu, bx.y, bp);
                float kx2 = __shfl_sync(0xFFFFFFFFu, bx.z, bp);
                float ky2 = __shfl_sync(0xFFFFFFFFu, bx.w, bp);
                if (lane == 0) s_kept[nk] = make_float4(kx1,ky1,kx2,ky2);
                nk++;
                alivemask &= ~(1u << bp);
                if (!alivemask || nk == POST) break;
                float ka = (kx2-kx1+1.0f)*(ky2-ky1+1.0f);
                float xx1=fmaxf(kx1,bx.x), yy1=fmaxf(ky1,bx.y);
                float xx2=fminf(kx2,bx.z), yy2=fminf(ky2,bx.w);
                float inter = fmaxf(xx2-xx1+1.0f,0.0f)*fmaxf(yy2-yy1+1.0f,0.0f);
                float iou = inter / fmaxf(ka + area - inter, 1e-6f);
                alivemask &= ~__ballot_sync(0xFFFFFFFFu, iou > NMS_T);
            }
            if (lane == 0) s_nk = nk;
        }
        __syncthreads();
        nk = s_nk;
        if (nk >= POST) break;
    }

    if (tid < POST){
        int row = (b*POST + tid)*5;
        float4 kb = (tid < nk) ? s_kept[tid] : make_float4(0.f,0.f,0.f,0.f);
        out[row+0] = (float)b;
        out[row+1] = kb.x; out[row+2] = kb.y; out[row+3] = kb.z; out[row+4] = kb.w;
    }
}

// ---------------- launcher ----------------
extern "C" void kernel_launch(void* const* d_in, const int* in_sizes, int n_in,
                              void* d_out, int out_size){
    const float* cls  = (const float*)d_in[0];
    const float* pred = (const float*)d_in[1];
    const float* info = (const float*)d_in[2];
    float* out = (float*)d_out;

    cudaFuncSetAttribute(k_sort, cudaFuncAttributeMaxDynamicSharedMemorySize, CAP*8);

    k_init<<<BB*NBIN/1024, 1024>>>();
    k_hist<<<dim3(9, BB), 1024>>>(cls);
    k_thresh<<<BB, 1024>>>();
    k_compact<<<dim3(9, BB), 1024>>>(cls, pred, info);
    k_sort<<<BB, 1024, CAP*8>>>(pred, info);
    k_nms<<<BB, NMST>>>(out);
}